// round 14
// baseline (speedup 1.0000x reference)
#include <cuda_runtime.h>
#include <cuda_bf16.h>
#include <cstdint>

// ============================================================================
// Baseline-PTX tensor-core helpers (sm_80+; compiles for plain sm_103 target)
// ============================================================================
__device__ __forceinline__ uint32_t smem_u32(const void* p) {
    uint32_t a;
    asm("{ .reg .u64 t; cvta.to.shared.u64 t, %1; cvt.u32.u64 %0, t; }"
        : "=r"(a) : "l"(p));
    return a;
}
__device__ __forceinline__ void ldsm_x4(uint32_t (&r)[4], uint32_t addr) {
    asm volatile("ldmatrix.sync.aligned.m8n8.x4.shared.b16 {%0,%1,%2,%3}, [%4];"
                 : "=r"(r[0]), "=r"(r[1]), "=r"(r[2]), "=r"(r[3]) : "r"(addr));
}
__device__ __forceinline__ void mma_bf16(float (&d)[4], const uint32_t (&a)[4],
                                         uint32_t b0, uint32_t b1) {
    asm volatile(
        "mma.sync.aligned.m16n8k16.row.col.f32.bf16.bf16.f32 "
        "{%0,%1,%2,%3}, {%4,%5,%6,%7}, {%8,%9}, {%0,%1,%2,%3};"
        : "+f"(d[0]), "+f"(d[1]), "+f"(d[2]), "+f"(d[3])
        : "r"(a[0]), "r"(a[1]), "r"(a[2]), "r"(a[3]), "r"(b0), "r"(b1));
}
__device__ __forceinline__ uint32_t pack_bf16(__nv_bfloat16 a, __nv_bfloat16 b) {
    uint32_t lo = (uint32_t)__bfloat16_as_ushort(a);
    uint32_t hi = (uint32_t)__bfloat16_as_ushort(b);
    return (hi << 16) | lo;
}

// ============================================================================
// Wt hi/lo split, transposed to [n][k] (B col-major for row.col mma)
// ============================================================================
__device__ __nv_bfloat16 g_wt_hi[128 * 256];
__device__ __nv_bfloat16 g_wt_lo[128 * 256];

__global__ void prep_kernel(const float* __restrict__ W) {   // W [256 k][128 n]
    int idx = blockIdx.x * blockDim.x + threadIdx.x;         // 0..32767
    if (idx >= 256 * 128) return;
    int k = idx >> 7;
    int n = idx & 127;
    float w = W[idx];
    __nv_bfloat16 hi = __float2bfloat16(w);
    __nv_bfloat16 lo = __float2bfloat16(w - __bfloat162float(hi));
    g_wt_hi[n * 256 + k] = hi;
    g_wt_lo[n * 256 + k] = lo;
}

// ============================================================================
// Phase 1: h = inputs @ W, mma.sync bf16 two-term split (HH + HL + LH), fp32 acc
// CTA: 128 rows x 128 cols, K=256 in 4 chunks of 64. 8 warps (4m x 2n),
// warp tile 32x64 = 2 x 8 m16n8k16 fragments. B ldsm paired into x4.
// ============================================================================
#define LDT 72            // smem row stride in bf16 (64 + 8 pad: LDSM conflict-free)
static constexpr int SM_AHI = 0;
static constexpr int SM_ALO = SM_AHI + 128 * LDT * 2;   // 18432
static constexpr int SM_BHI = SM_ALO + 128 * LDT * 2;
static constexpr int SM_BLO = SM_BHI + 128 * LDT * 2;
static constexpr int SM_TOTAL = SM_BLO + 128 * LDT * 2; // 73728

__global__ __launch_bounds__(256)
void gemm_mma_kernel(const float* __restrict__ A,   // [M, 256]
                     float* __restrict__ C,         // [M, 128]
                     int M) {
    extern __shared__ char smem[];
    const uint32_t sb = smem_u32(smem);
    const int tid = threadIdx.x;
    const int wid = tid >> 5;
    const int lane = tid & 31;
    const int block_row = blockIdx.x * 128;

    const int warp_m = wid & 3;          // 0..3 -> 32-row slab
    const int warp_n = wid >> 2;         // 0..1 -> 64-col slab

    float acc[2][8][4];
    #pragma unroll
    for (int mt = 0; mt < 2; mt++)
        #pragma unroll
        for (int nt = 0; nt < 8; nt++)
            #pragma unroll
            for (int j = 0; j < 4; j++)
                acc[mt][nt][j] = 0.0f;

    const uint32_t* wh32 = (const uint32_t*)g_wt_hi;
    const uint32_t* wl32 = (const uint32_t*)g_wt_lo;

    // A x4 geometry (fragment order a0=[r0-7,k0-7], a1=[r8-15,k0-7],
    //                a2=[r0-7,k8-15], a3=[r8-15,k8-15]):
    //   lanes 0-15 -> rows 0-15 col 0;  lanes 16-31 -> rows 0-15 col 8.
    const int a_r = (lane & 15);
    const int a_c = ((lane >> 4) << 3);
    // B x4 geometry (two n-tiles per load: m0/m1 = tile 2np (k0-7 / k8-15),
    //                m2/m3 = tile 2np+1):
    //   lanes 0-7 -> rows 0-7 col 0;   lanes 8-15  -> rows 0-7 col 8;
    //   lanes 16-23 -> rows 8-15 col 0; lanes 24-31 -> rows 8-15 col 8.
    const int b_r = ((lane >> 4) << 3) + (lane & 7);
    const int b_c = ((lane >> 3) & 1) << 3;

    #pragma unroll 1
    for (int c = 0; c < 4; c++) {
        if (c > 0) __syncthreads();      // smem reuse: previous mma must be done

        // ---- stage A chunk: fp32 -> bf16 hi/lo into smem ----
        #pragma unroll
        for (int i = 0; i < 16; i++) {
            int p = tid + 256 * i;            // pair index 0..4095
            int r = p >> 5;                   // row 0..127
            int c2 = (p & 31) << 1;           // even k-col 0..62
            int grow = block_row + r;
            if (grow >= M) grow = M - 1;
            float2 v = *(const float2*)(A + (size_t)grow * 256 + c * 64 + c2);
            __nv_bfloat16 h0 = __float2bfloat16(v.x);
            __nv_bfloat16 h1 = __float2bfloat16(v.y);
            __nv_bfloat16 l0 = __float2bfloat16(v.x - __bfloat162float(h0));
            __nv_bfloat16 l1 = __float2bfloat16(v.y - __bfloat162float(h1));
            uint32_t off = (uint32_t)(r * LDT + c2) * 2;
            *(uint32_t*)(smem + SM_AHI + off) = pack_bf16(h0, h1);
            *(uint32_t*)(smem + SM_ALO + off) = pack_bf16(l0, l1);
        }
        // ---- stage B chunk: copy Wt hi/lo (bf16, [n][k]) into padded smem ----
        #pragma unroll
        for (int i = 0; i < 16; i++) {
            int p = tid + 256 * i;
            int n = p >> 5;                   // n row 0..127
            int kk = p & 31;                  // uint32 (bf16 pair) index in chunk
            int gidx = n * 128 + c * 32 + kk;
            uint32_t off = (uint32_t)(n * LDT + (kk << 1)) * 2;
            *(uint32_t*)(smem + SM_BHI + off) = wh32[gidx];
            *(uint32_t*)(smem + SM_BLO + off) = wl32[gidx];
        }
        __syncthreads();

        // ---- mma over 4 K-steps of 16 ----
        #pragma unroll
        for (int s = 0; s < 4; s++) {
            const int k0 = s * 16;
            uint32_t ah[2][4], al[2][4];
            #pragma unroll
            for (int mt = 0; mt < 2; mt++) {
                int row = warp_m * 32 + mt * 16 + a_r;
                uint32_t off = (uint32_t)(row * LDT + k0 + a_c) * 2;
                ldsm_x4(ah[mt], sb + SM_AHI + off);
                ldsm_x4(al[mt], sb + SM_ALO + off);
            }
            #pragma unroll
            for (int np = 0; np < 4; np++) {         // nt pair {2np, 2np+1}
                int nrow = warp_n * 64 + np * 16 + b_r;
                uint32_t off = (uint32_t)(nrow * LDT + k0 + b_c) * 2;
                uint32_t bh[4], bl[4];
                ldsm_x4(bh, sb + SM_BHI + off);
                ldsm_x4(bl, sb + SM_BLO + off);
                #pragma unroll
                for (int mt = 0; mt < 2; mt++) {
                    mma_bf16(acc[mt][2 * np],     ah[mt], bh[0], bh[1]);  // HH
                    mma_bf16(acc[mt][2 * np],     ah[mt], bl[0], bl[1]);  // HL
                    mma_bf16(acc[mt][2 * np],     al[mt], bh[0], bh[1]);  // LH
                    mma_bf16(acc[mt][2 * np + 1], ah[mt], bh[2], bh[3]);  // HH
                    mma_bf16(acc[mt][2 * np + 1], ah[mt], bl[2], bl[3]);  // HL
                    mma_bf16(acc[mt][2 * np + 1], al[mt], bh[2], bh[3]);  // LH
                }
            }
        }
    }

    // ---- epilogue: c-frag layout -> global fp32 stores ----
    const int rbase = block_row + warp_m * 32 + (lane >> 2);
    const int cbase = warp_n * 64 + ((lane & 3) << 1);
    #pragma unroll
    for (int mt = 0; mt < 2; mt++) {
        int r0 = rbase + mt * 16;
        int r1 = r0 + 8;
        #pragma unroll
        for (int nt = 0; nt < 8; nt++) {
            int col = cbase + nt * 8;
            if (r0 < M)
                *(float2*)(C + (size_t)r0 * 128 + col) =
                    make_float2(acc[mt][nt][0], acc[mt][nt][1]);
            if (r1 < M)
                *(float2*)(C + (size_t)r1 * 128 + col) =
                    make_float2(acc[mt][nt][2], acc[mt][nt][3]);
        }
    }
}

// ----------------------------------------------------------------------------
// Phase 2: edge_weight[e] = relu( sum_k |h[u,k]-h[v,k]| * a[k] )
// 4 edges/warp. Gathers use 32-bit loads where all 32 lanes hit ONE 128B line
// (lane l reads h[row*128 + j*32 + l], j=0..3): single-line LDGs at the
// cross-LDG L1tex wavefront rate (1.0 cyc/wf) instead of 4-line LDG.128s at
// the within-LDG replay rate (2.07 cyc/wf). __ldcg: h is L2-resident.
// ----------------------------------------------------------------------------
__global__ __launch_bounds__(256)
void edge_kernel(const float* __restrict__ h,    // [M, 128]
                 const int* __restrict__ edge,   // [2, E] int32
                 const float* __restrict__ a,    // [128]
                 float* __restrict__ ew,         // [E]
                 int E) {
    const int warp = (blockIdx.x * blockDim.x + threadIdx.x) >> 5;
    const int lane = threadIdx.x & 31;
    const int e0 = warp * 4;
    if (e0 >= E) return;

    // a[j*32 + lane] for j=0..3 (matches the strided gather mapping)
    float av[4];
    #pragma unroll
    for (int j = 0; j < 4; j++) av[j] = __ldg(a + j * 32 + lane);

    const int4 uu = __ldg((const int4*)(edge) + warp);
    const int4 vv = __ldg((const int4*)(edge + (size_t)E) + warp);
    const int u[4] = {uu.x, uu.y, uu.z, uu.w};
    const int v[4] = {vv.x, vv.y, vv.z, vv.w};

    // 32 single-line gathers, all issued before consumption (deep MLP)
    float hu[4][4], hv[4][4];
    #pragma unroll
    for (int i = 0; i < 4; i++) {
        const float* pu = h + (size_t)u[i] * 128 + lane;
        const float* pv = h + (size_t)v[i] * 128 + lane;
        #pragma unroll
        for (int j = 0; j < 4; j++) {
            hu[i][j] = __ldcg(pu + j * 32);
            hv[i][j] = __ldcg(pv + j * 32);
        }
    }

    float s[4];
    #pragma unroll
    for (int i = 0; i < 4; i++) {
        float t = 0.0f;
        #pragma unroll
        for (int j = 0; j < 4; j++)
            t = fmaf(fabsf(hu[i][j] - hv[i][j]), av[j], t);
        s[i] = t;
    }

    #pragma unroll
    for (int o = 16; o > 0; o >>= 1) {
        #pragma unroll
        for (int i = 0; i < 4; i++)
            s[i] += __shfl_xor_sync(0xFFFFFFFFu, s[i], o);
    }

    if (lane < 4) {
        int e = e0 + lane;
        if (e < E) ew[e] = fmaxf(s[lane], 0.0f);
    }
}

// ----------------------------------------------------------------------------
// Launch: prep (W -> bf16 hi/lo [n][k]) -> mma.sync GEMM -> edge kernel
// Output: concat( h [M*128], edge_weight [E] ) fp32
// ----------------------------------------------------------------------------
extern "C" void kernel_launch(void* const* d_in, const int* in_sizes, int n_in,
                              void* d_out, int out_size) {
    const float* inputs = (const float*)d_in[0];
    const int*   edge   = (const int*)d_in[1];
    const float* weight = (const float*)d_in[2];
    const float* a      = (const float*)d_in[3];

    const int M = in_sizes[0] / 256;
    const int E = in_sizes[1] / 2;

    float* h  = (float*)d_out;
    float* ew = (float*)d_out + (size_t)M * 128;

    cudaFuncSetAttribute(gemm_mma_kernel,
                         cudaFuncAttributeMaxDynamicSharedMemorySize, SM_TOTAL);

    prep_kernel<<<128, 256>>>(weight);

    int gemm_blocks = (M + 127) / 128;
    gemm_mma_kernel<<<gemm_blocks, 256, SM_TOTAL>>>(inputs, h, M);

    int edge_blocks = (E + 31) / 32;
    edge_kernel<<<edge_blocks, 256>>>(h, edge, a, ew, E);
}